// round 8
// baseline (speedup 1.0000x reference)
#include <cuda_runtime.h>
#include <math.h>

#define HW    2304
#define MV    4608
#define CHN   64
#define NT2C  48
#define NOCC  1024
#define NA    1048
#define GTRI  148
#define TPB   256

__device__ float g_t [CHN*HW];
__device__ float g_a [CHN*HW];
__device__ float g_h0[CHN*HW];
__device__ float g_h1[CHN*HW];
__device__ float g_A[(size_t)NA*NA];
__device__ float g_u[NA];
__device__ int   g_n[NOCC];
__device__ float g_logJ;
__device__ unsigned g_cnt = 0;
__device__ volatile unsigned g_gen;

__device__ __forceinline__ float gelu_f(float x) {
    float x3 = x * x * x;
    return 0.5f * x * (1.f + tanhf(0.7978845608028654f * (x + 0.044715f * x3)));
}

__device__ __forceinline__ float warp_sum(float v) {
    #pragma unroll
    for (int o = 16; o > 0; o >>= 1) v += __shfl_down_sync(0xffffffffu, v, o);
    return v;
}

__device__ __forceinline__ void gridbar() {
    __syncthreads();
    if (threadIdx.x == 0) {
        __threadfence();
        unsigned gen = g_gen;
        unsigned a = atomicAdd(&g_cnt, 1u);
        if (a == gridDim.x - 1) {
            g_cnt = 0;
            __threadfence();
            g_gen = gen + 1;
        } else {
            while (g_gen == gen) { }
        }
        __threadfence();
    }
    __syncthreads();
}

__global__ void pre0_kernel(const float* __restrict__ x) {
    int i = blockIdx.x * blockDim.x + threadIdx.x;
    if (i < 2 * HW) g_t[i] = x[i] * 0.7071067811865475f;
}

__global__ void pre_kernel(const float* __restrict__ h, float scale) {
    int i = blockIdx.x * blockDim.x + threadIdx.x;
    if (i < CHN * HW) g_t[i] = gelu_f(h[i] * scale);
}

__global__ void scale_kernel(const float* __restrict__ h) {
    int i = blockIdx.x * blockDim.x + threadIdx.x;
    if (i < CHN * HW) g_a[i] = h[i] * 0.4472135954999579f;
}

__global__ void conv_kernel(const float* __restrict__ xin, int IC,
                            const float* __restrict__ w,
                            const float* __restrict__ bias,
                            const float* __restrict__ res, int res_shift,
                            int do_gelu,
                            float* __restrict__ yout)
{
    __shared__ float sw[CHN * 9];
    int o = blockIdx.x;
    int t = threadIdx.x;
    for (int i = t; i < IC * 9; i += blockDim.x) sw[i] = w[o * IC * 9 + i];
    __syncthreads();

    int idx = blockIdx.y * 128 + t;
    int row = idx >> 4;
    int c0  = (idx & 15) * 3;
    int rm = (row == 0)  ? 47 : row - 1;
    int rp = (row == 47) ? 0  : row + 1;
    int cm = (c0 == 0)   ? 47 : c0 - 1;
    int c3 = (c0 == 45)  ? 0  : c0 + 3;

    float a0 = 0.f, a1 = 0.f, a2 = 0.f;
    int rows3[3] = { rm, row, rp };
    for (int ic = 0; ic < IC; ic++) {
        const float* xp = xin + ic * HW;
        const float* wp = sw + ic * 9;
        #pragma unroll
        for (int rr = 0; rr < 3; rr++) {
            const float* xr = xp + rows3[rr] * 48;
            float xa = xr[cm], xb = xr[c0], xc = xr[c0 + 1], xd = xr[c0 + 2], xe = xr[c3];
            float w0 = wp[rr * 3], w1 = wp[rr * 3 + 1], w2 = wp[rr * 3 + 2];
            a0 += w0 * xa + w1 * xb + w2 * xc;
            a1 += w0 * xb + w1 * xc + w2 * xd;
            a2 += w0 * xc + w1 * xd + w2 * xe;
        }
    }
    float bb = bias ? bias[o] : 0.f;
    a0 += bb; a1 += bb; a2 += bb;
    if (do_gelu) { a0 = gelu_f(a0); a1 = gelu_f(a1); a2 = gelu_f(a2); }
    int p = row * 48 + c0;
    if (res) {
        const float* rr_ = res + (o >> res_shift) * HW;
        a0 += rr_[p]; a1 += rr_[p + 1]; a2 += rr_[p + 2];
    }
    float* yp = yout + o * HW + p;
    yp[0] = a0; yp[1] = a1; yp[2] = a2;
}

__global__ void logj_kernel() {
    int t = threadIdx.x;
    float p = 0.f;
    for (int i = NT2C * HW + t; i < CHN * HW; i += TPB) p += g_a[i];
    p = warp_sum(p);
    __shared__ float sp[8];
    if ((t & 31) == 0) sp[t >> 5] = p;
    __syncthreads();
    if (t == 0) {
        float s = 0.f;
        for (int q = 0; q < 8; q++) s += sp[q];
        g_logJ = s;
    }
}

__global__ void nonzero_kernel(const float* __restrict__ x) {
    __shared__ int sc[1024];
    __shared__ int sbase;
    int t = threadIdx.x;
    if (t == 0) sbase = 0;
    __syncthreads();
    for (int c = 0; c < 5; c++) {
        int i = c * 1024 + t;
        int f = (i < MV && x[i] > 0.f) ? 1 : 0;
        sc[t] = f;
        __syncthreads();
        for (int off = 1; off < 1024; off <<= 1) {
            int v = (t >= off) ? sc[t - off] : 0;
            __syncthreads();
            sc[t] += v;
            __syncthreads();
        }
        if (f) {
            int pos = sbase + sc[t] - 1;
            if (pos < NOCC) g_n[pos] = i;
        }
        __syncthreads();
        if (t == 0) sbase += sc[1023];
        __syncthreads();
    }
}

__global__ void buildA_kernel(const float* __restrict__ Fvv,
                              const float* __restrict__ Fhh)
{
    int i = blockIdx.x;
    float* Ar = g_A + (size_t)i * NA;
    if (i < NOCC) {
        int ni = g_n[i];
        for (int j = threadIdx.x; j < NA; j += TPB) {
            float v;
            if (j < NOCC) {
                int nj = g_n[j];
                v = 0.5f * (Fvv[(size_t)ni * MV + nj] - Fvv[(size_t)nj * MV + ni]);
            } else {
                v = g_a[(j - NOCC) * MV + ni];
            }
            Ar[j] = v;
        }
    } else {
        int a = i - NOCC;
        for (int j = threadIdx.x; j < NA; j += TPB) {
            float v;
            if (j < NOCC) {
                int nj = g_n[j];
                v = -g_a[a * MV + nj];
            } else {
                int b = j - NOCC;
                v = 0.5f * (Fhh[a * 24 + b] - Fhh[b * 24 + a]);
            }
            Ar[j] = v;
        }
    }
}

__global__ void __launch_bounds__(TPB, 1) tridiag_kernel(float* __restrict__ out)
{
    const int cta = blockIdx.x, t = threadIdx.x;
    const int w = t >> 5, lane = t & 31;
    __shared__ float sv[NA];
    __shared__ float su[NA];
    __shared__ float sp[8];
    __shared__ float s_norm2;

    float sign_acc = 1.f;
    double logs = 0.0;

    for (int k = 0; k < NA - 2; k++) {
        const int base = k + 1;
        const float* rowk = g_A + (size_t)k * NA;
        float part = 0.f;
        for (int j = base + t; j < NA; j += TPB) {
            float xx = -__ldcg(rowk + j);
            sv[j] = xx;
            part += xx * xx;
        }
        part = warp_sum(part);
        if (lane == 0) sp[w] = part;
        __syncthreads();
        if (t == 0) {
            float a = 0.f;
            for (int q = 0; q < 8; q++) a += sp[q];
            s_norm2 = a;
        }
        __syncthreads();
        float norm2 = s_norm2;
        float x1 = sv[base];
        float s = (x1 >= 0.f) ? 1.f : -1.f;
        float normx = sqrtf(norm2);
        float vnsq = 2.f * norm2 + 2.f * s * normx * x1;
        bool ok = (vnsq > 0.f);
        float inv = ok ? rsqrtf(vnsq) : 0.f;

        if (ok) sign_acc = -sign_acc;
        if ((k & 1) == 0) {
            sign_acc *= s;
            logs += log((double)normx);
        }

        __syncthreads();
        if (t == 0) sv[base] = x1 + s * normx;
        for (int j = base + t; j < NA; j += TPB) sv[j] *= inv;
        __syncthreads();

        int gw = cta * 8 + w;
        int j = base + gw;
        if (j < NA) {
            const float* rj = g_A + (size_t)j * NA;
            float acc = 0.f;
            for (int l = base + lane; l < NA; l += 32)
                acc += __ldcg(rj + l) * sv[l];
            acc = warp_sum(acc);
            if (lane == 0) __stcg(g_u + j, acc);
        }
        gridbar();

        for (int l2 = base + t; l2 < NA; l2 += TPB) su[l2] = __ldcg(g_u + l2);
        __syncthreads();
        if (j < NA) {
            float vj = sv[j], uj = su[j];
            float* rj = g_A + (size_t)j * NA;
            for (int l = base + lane; l < NA; l += 32) {
                float a = __ldcg(rj + l);
                a += 2.f * (vj * su[l] - uj * sv[l]);
                __stcg(rj + l, a);
            }
        }
        gridbar();
    }

    if (cta == 0 && t == 0) {
        float aL = __ldcg(&g_A[(size_t)(NA - 2) * NA + (NA - 1)]);
        float sgn = sign_acc * ((aL >= 0.f) ? 1.f : -1.f);
        double tot = logs + log(fabs((double)aL)) + (double)g_logJ;
        out[0] = sgn;
        out[1] = (float)tot;
    }
}

extern "C" void kernel_launch(void* const* d_in, const int* in_sizes, int n_in,
                              void* d_out, int out_size) {
    const float* x   = (const float*)d_in[0];
    const float* Fvv = (const float*)d_in[1];
    const float* Fhh = (const float*)d_in[2];
    const float* w1_0 = (const float*)d_in[3];
    const float* b1_0 = (const float*)d_in[4];
    const float* w2_0 = (const float*)d_in[5];
    const float* b2_0 = (const float*)d_in[6];
    const float* w1_1 = (const float*)d_in[7];
    const float* b1_1 = (const float*)d_in[8];
    const float* w2_1 = (const float*)d_in[9];
    const float* b2_1 = (const float*)d_in[10];
    const float* w1_2 = (const float*)d_in[11];
    const float* b1_2 = (const float*)d_in[12];
    const float* w2_2 = (const float*)d_in[13];
    const float* b2_2 = (const float*)d_in[14];
    const float* w1_3 = (const float*)d_in[15];
    const float* b1_3 = (const float*)d_in[16];
    const float* w2_3 = (const float*)d_in[17];

    float *p_t, *p_a, *p_h0, *p_h1;
    cudaGetSymbolAddress((void**)&p_t,  g_t);
    cudaGetSymbolAddress((void**)&p_a,  g_a);
    cudaGetSymbolAddress((void**)&p_h0, g_h0);
    cudaGetSymbolAddress((void**)&p_h1, g_h1);

    dim3 cg(CHN, 6);
    const int EB = (CHN * HW + 255) / 256;

    pre0_kernel<<<(2 * HW + 255) / 256, 256>>>(x);
    conv_kernel<<<cg, 128>>>(p_t, 2,   w1_0, b1_0, nullptr, 0, 1, p_a);
    conv_kernel<<<cg, 128>>>(p_a, CHN, w2_0, b2_0, x,       5, 0, p_h0);

    pre_kernel<<<EB, 256>>>(p_h0, 0.7071067811865475f);
    conv_kernel<<<cg, 128>>>(p_t, CHN, w1_1, b1_1, nullptr, 0, 1, p_a);
    conv_kernel<<<cg, 128>>>(p_a, CHN, w2_1, b2_1, p_h0,    0, 0, p_h1);

    pre_kernel<<<EB, 256>>>(p_h1, 0.5773502691896258f);
    conv_kernel<<<cg, 128>>>(p_t, CHN, w1_2, b1_2, nullptr, 0, 1, p_a);
    conv_kernel<<<cg, 128>>>(p_a, CHN, w2_2, b2_2, p_h1,    0, 0, p_h0);

    pre_kernel<<<EB, 256>>>(p_h0, 0.5f);
    conv_kernel<<<cg, 128>>>(p_t, CHN, w1_3, b1_3, nullptr, 0, 1, p_a);
    conv_kernel<<<cg, 128>>>(p_a, CHN, w2_3, nullptr, p_h0, 0, 0, p_h1);

    scale_kernel<<<EB, 256>>>(p_h1);
    logj_kernel<<<1, TPB>>>();
    nonzero_kernel<<<1, 1024>>>(x);
    buildA_kernel<<<NA, TPB>>>(Fvv, Fhh);
    tridiag_kernel<<<GTRI, TPB>>>((float*)d_out);
}

// round 9
// speedup vs baseline: 1.1733x; 1.1733x over previous
#include <cuda_runtime.h>
#include <math.h>

#define HW    2304
#define MV    4608
#define CHN   64
#define NT2C  48
#define NOCC  1024
#define NA    1048
#define GTRI  148
#define TPB   256

__device__ float g_t [CHN*HW];
__device__ float g_a [CHN*HW];
__device__ float g_h0[CHN*HW];
__device__ float g_h1[CHN*HW];
__device__ float g_A[(size_t)NA*NA];
__device__ float g_u2[2][NA];
__device__ int   g_n[NOCC];
__device__ float g_logJ;
__device__ unsigned g_cnt = 0;
__device__ volatile unsigned g_gen;

__device__ __forceinline__ float gelu_f(float x) {
    float x3 = x * x * x;
    return 0.5f * x * (1.f + tanhf(0.7978845608028654f * (x + 0.044715f * x3)));
}

__device__ __forceinline__ float warp_sum(float v) {
    #pragma unroll
    for (int o = 16; o > 0; o >>= 1) v += __shfl_down_sync(0xffffffffu, v, o);
    return v;
}

__device__ __forceinline__ void gridbar() {
    __syncthreads();
    if (threadIdx.x == 0) {
        __threadfence();
        unsigned gen = g_gen;
        unsigned a = atomicAdd(&g_cnt, 1u);
        if (a == gridDim.x - 1) {
            g_cnt = 0;
            __threadfence();
            g_gen = gen + 1;
        } else {
            while (g_gen == gen) { }
        }
        __threadfence();
    }
    __syncthreads();
}

// ----------------------------- CNN ----------------------------------------
__global__ void pre0_kernel(const float* __restrict__ x) {
    int i = blockIdx.x * blockDim.x + threadIdx.x;
    if (i < 2 * HW) g_t[i] = x[i] * 0.7071067811865475f;
}

__global__ void pre_kernel(const float* __restrict__ h, float scale) {
    int i = blockIdx.x * blockDim.x + threadIdx.x;
    if (i < CHN * HW) g_t[i] = gelu_f(h[i] * scale);
}

__global__ void scale_kernel(const float* __restrict__ h) {
    int i = blockIdx.x * blockDim.x + threadIdx.x;
    if (i < CHN * HW) g_a[i] = h[i] * 0.4472135954999579f;
}

__global__ void conv_kernel(const float* __restrict__ xin, int IC,
                            const float* __restrict__ w,
                            const float* __restrict__ bias,
                            const float* __restrict__ res, int res_shift,
                            int do_gelu,
                            float* __restrict__ yout)
{
    __shared__ float sw[CHN * 9];
    int o = blockIdx.x;
    int t = threadIdx.x;
    for (int i = t; i < IC * 9; i += blockDim.x) sw[i] = w[o * IC * 9 + i];
    __syncthreads();

    int idx = blockIdx.y * 128 + t;
    int row = idx >> 4;
    int c0  = (idx & 15) * 3;
    int rm = (row == 0)  ? 47 : row - 1;
    int rp = (row == 47) ? 0  : row + 1;
    int cm = (c0 == 0)   ? 47 : c0 - 1;
    int c3 = (c0 == 45)  ? 0  : c0 + 3;

    float a0 = 0.f, a1 = 0.f, a2 = 0.f;
    int rows3[3] = { rm, row, rp };
    for (int ic = 0; ic < IC; ic++) {
        const float* xp = xin + ic * HW;
        const float* wp = sw + ic * 9;
        #pragma unroll
        for (int rr = 0; rr < 3; rr++) {
            const float* xr = xp + rows3[rr] * 48;
            float xa = xr[cm], xb = xr[c0], xc = xr[c0 + 1], xd = xr[c0 + 2], xe = xr[c3];
            float w0 = wp[rr * 3], w1 = wp[rr * 3 + 1], w2 = wp[rr * 3 + 2];
            a0 += w0 * xa + w1 * xb + w2 * xc;
            a1 += w0 * xb + w1 * xc + w2 * xd;
            a2 += w0 * xc + w1 * xd + w2 * xe;
        }
    }
    float bb = bias ? bias[o] : 0.f;
    a0 += bb; a1 += bb; a2 += bb;
    if (do_gelu) { a0 = gelu_f(a0); a1 = gelu_f(a1); a2 = gelu_f(a2); }
    int p = row * 48 + c0;
    if (res) {
        const float* rr_ = res + (o >> res_shift) * HW;
        a0 += rr_[p]; a1 += rr_[p + 1]; a2 += rr_[p + 2];
    }
    float* yp = yout + o * HW + p;
    yp[0] = a0; yp[1] = a1; yp[2] = a2;
}

__global__ void logj_kernel() {
    int t = threadIdx.x;
    float p = 0.f;
    for (int i = NT2C * HW + t; i < CHN * HW; i += TPB) p += g_a[i];
    p = warp_sum(p);
    __shared__ float sp[8];
    if ((t & 31) == 0) sp[t >> 5] = p;
    __syncthreads();
    if (t == 0) {
        float s = 0.f;
        for (int q = 0; q < 8; q++) s += sp[q];
        g_logJ = s;
    }
}

__global__ void nonzero_kernel(const float* __restrict__ x) {
    __shared__ int sc[1024];
    __shared__ int sbase;
    int t = threadIdx.x;
    if (t == 0) sbase = 0;
    __syncthreads();
    for (int c = 0; c < 5; c++) {
        int i = c * 1024 + t;
        int f = (i < MV && x[i] > 0.f) ? 1 : 0;
        sc[t] = f;
        __syncthreads();
        for (int off = 1; off < 1024; off <<= 1) {
            int v = (t >= off) ? sc[t - off] : 0;
            __syncthreads();
            sc[t] += v;
            __syncthreads();
        }
        if (f) {
            int pos = sbase + sc[t] - 1;
            if (pos < NOCC) g_n[pos] = i;
        }
        __syncthreads();
        if (t == 0) sbase += sc[1023];
        __syncthreads();
    }
}

__global__ void buildA_kernel(const float* __restrict__ Fvv,
                              const float* __restrict__ Fhh)
{
    int i = blockIdx.x;
    float* Ar = g_A + (size_t)i * NA;
    if (i < NOCC) {
        int ni = g_n[i];
        for (int j = threadIdx.x; j < NA; j += TPB) {
            float v;
            if (j < NOCC) {
                int nj = g_n[j];
                v = 0.5f * (Fvv[(size_t)ni * MV + nj] - Fvv[(size_t)nj * MV + ni]);
            } else {
                v = g_a[(j - NOCC) * MV + ni];
            }
            Ar[j] = v;
        }
    } else {
        int a = i - NOCC;
        for (int j = threadIdx.x; j < NA; j += TPB) {
            float v;
            if (j < NOCC) {
                int nj = g_n[j];
                v = -g_a[a * MV + nj];
            } else {
                int b = j - NOCC;
                v = 0.5f * (Fhh[a * 24 + b] - Fhh[b * 24 + a]);
            }
            Ar[j] = v;
        }
    }
}

// ---------------- persistent skew-Householder tridiagonalization -----------
// One grid barrier per step. Fused pass: each warp owns one trailing row,
// applies the rank-2 update for step k and accumulates the matvec for step
// k+1 in a single LDG.128/STG.128 sweep. v_{k+1} is rebuilt redundantly per
// CTA from the stale pivot row + rank-2 correction. u is double-buffered.
// All A/u traffic is __ldcg/__stcg (L2-only): row ownership rotates across
// CTAs and L1 is not coherent.
__global__ void __launch_bounds__(TPB, 1) tridiag_kernel(float* __restrict__ out)
{
    const int cta = blockIdx.x, t = threadIdx.x;
    const int w = t >> 5, lane = t & 31;
    __shared__ float sv[2][NA];     // v_k (parity k&1) and v_{k+1}
    __shared__ float su[NA];        // u_k
    __shared__ float sp[8];
    __shared__ float s_red;

    float sign_acc = 1.f;
    double logs = 0.0;

    // ---- pre-step: build v_0 from row 0 and compute u_0 = A v_0 (no update)
    {
        const float* row0 = g_A;
        float part = 0.f;
        for (int j = 1 + t; j < NA; j += TPB) {
            float xx = -__ldcg(row0 + j);
            sv[0][j] = xx;
            part += xx * xx;
        }
        if (t == 0) sv[0][0] = 0.f;
        part = warp_sum(part);
        if (lane == 0) sp[w] = part;
        __syncthreads();
        if (t == 0) { float a = 0.f; for (int q = 0; q < 8; q++) a += sp[q]; s_red = a; }
        __syncthreads();
        float norm2 = s_red;
        float x1 = sv[0][1];
        float s = (x1 >= 0.f) ? 1.f : -1.f;
        float normx = sqrtf(norm2);
        float vnsq = 2.f * norm2 + 2.f * s * normx * x1;
        bool ok = (vnsq > 0.f);
        float inv = ok ? rsqrtf(vnsq) : 0.f;
        if (ok) sign_acc = -sign_acc;
        sign_acc *= s;                         // k=0 even
        logs += log((double)normx);
        __syncthreads();
        if (t == 0) sv[0][1] = x1 + s * normx;
        for (int j = 1 + t; j < NA; j += TPB) sv[0][j] *= inv;
        __syncthreads();

        int j = 1 + cta * 8 + w;
        if (j < NA) {
            const float* rj = g_A + (size_t)j * NA;
            float acc = 0.f;
            for (int l = lane * 4; l < NA; l += 128) {
                float4 a4 = __ldcg((const float4*)(rj + l));
                acc += a4.x * sv[0][l] + a4.y * sv[0][l + 1]
                     + a4.z * sv[0][l + 2] + a4.w * sv[0][l + 3];
            }
            acc = warp_sum(acc);
            if (lane == 0) __stcg(&g_u2[0][j], acc);
        }
        gridbar();
    }

    // ---- main loop: iteration k applies update k and produces v_{k+1}, u_{k+1}
    for (int k = 0; k < NA - 3; k++) {
        const int base2 = k + 2;
        const int cur = k & 1, nxt = cur ^ 1;
        float* sv_c = sv[cur];
        float* sv_n = sv[nxt];
        const int c0 = (k + 1) & ~3;           // aligned start covering col k+1

        // -- load u_k into smem (whole buffer, float4); zero overhang [c0,k+1)
        for (int l = t * 4; l < NA; l += TPB * 4) {
            float4 u4 = __ldcg((const float4*)(&g_u2[cur][l]));
            *(float4*)(su + l) = u4;
        }
        if (t < 4) { int z = c0 + t; if (z < k + 1) su[z] = 0.f; }
        __syncthreads();

        // -- build v_{k+1} from stale row k+1 + rank-2 correction (redundant)
        const float vk1 = sv_c[k + 1];
        const float uk1 = su[k + 1];
        const float* rowp = g_A + (size_t)(k + 1) * NA;
        float part = 0.f;
        for (int l = base2 + t; l < NA; l += TPB) {
            float xx = -(__ldcg(rowp + l) + 2.f * (vk1 * su[l] - uk1 * sv_c[l]));
            sv_n[l] = xx;
            part += xx * xx;
        }
        if (t < 4) { int z = base2 - 4 + t; if (z >= 0) sv_n[z] = 0.f; }
        part = warp_sum(part);
        if (lane == 0) sp[w] = part;
        __syncthreads();
        if (t == 0) { float a = 0.f; for (int q = 0; q < 8; q++) a += sp[q]; s_red = a; }
        __syncthreads();
        float norm2 = s_red;
        float x1 = sv_n[base2];
        float s = (x1 >= 0.f) ? 1.f : -1.f;
        float normx = sqrtf(norm2);
        float vnsq = 2.f * norm2 + 2.f * s * normx * x1;
        bool ok = (vnsq > 0.f);
        float inv = ok ? rsqrtf(vnsq) : 0.f;
        if (ok) sign_acc = -sign_acc;
        if (((k + 1) & 1) == 0) {              // step k+1 even
            sign_acc *= s;
            logs += log((double)normx);
        }
        __syncthreads();                       // all read x1 before modify
        if (t == 0) sv_n[base2] = x1 + s * normx;
        for (int l = base2 + t; l < NA; l += TPB) sv_n[l] *= inv;
        __syncthreads();

        // -- fused pass: update row j (step k) + matvec with v_{k+1}
        int j = base2 + cta * 8 + w;
        if (j < NA) {
            float* rj = g_A + (size_t)j * NA;
            const float vj2 = 2.f * sv_c[j];
            const float uj2 = 2.f * su[j];
            float acc = 0.f;
            for (int l = c0 + lane * 4; l < NA; l += 128) {
                float4 a4 = __ldcg((const float4*)(rj + l));
                a4.x += vj2 * su[l]     - uj2 * sv_c[l];
                a4.y += vj2 * su[l + 1] - uj2 * sv_c[l + 1];
                a4.z += vj2 * su[l + 2] - uj2 * sv_c[l + 2];
                a4.w += vj2 * su[l + 3] - uj2 * sv_c[l + 3];
                __stcg((float4*)(rj + l), a4);
                acc += a4.x * sv_n[l]     + a4.y * sv_n[l + 1]
                     + a4.z * sv_n[l + 2] + a4.w * sv_n[l + 3];
            }
            acc = warp_sum(acc);
            if (lane == 0) __stcg(&g_u2[nxt][j], acc);
        }
        gridbar();
    }

    // ---- final step (k = NA-3): only element [NA-2, NA-1] matters
    if (cta == 0 && t == 0) {
        const int pl = (NA - 3) & 1;           // parity of last v/u
        float a_old = __ldcg(&g_A[(size_t)(NA - 2) * NA + (NA - 1)]);
        float v1 = sv[pl][NA - 2], v2 = sv[pl][NA - 1];
        float u1 = __ldcg(&g_u2[pl][NA - 2]);
        float u2 = __ldcg(&g_u2[pl][NA - 1]);
        float aL = a_old + 2.f * (v1 * u2 - u1 * v2);
        float sgn = sign_acc * ((aL >= 0.f) ? 1.f : -1.f);
        double tot = logs + log(fabs((double)aL)) + (double)g_logJ;
        out[0] = sgn;
        out[1] = (float)tot;
    }
}

extern "C" void kernel_launch(void* const* d_in, const int* in_sizes, int n_in,
                              void* d_out, int out_size) {
    const float* x   = (const float*)d_in[0];
    const float* Fvv = (const float*)d_in[1];
    const float* Fhh = (const float*)d_in[2];
    const float* w1_0 = (const float*)d_in[3];
    const float* b1_0 = (const float*)d_in[4];
    const float* w2_0 = (const float*)d_in[5];
    const float* b2_0 = (const float*)d_in[6];
    const float* w1_1 = (const float*)d_in[7];
    const float* b1_1 = (const float*)d_in[8];
    const float* w2_1 = (const float*)d_in[9];
    const float* b2_1 = (const float*)d_in[10];
    const float* w1_2 = (const float*)d_in[11];
    const float* b1_2 = (const float*)d_in[12];
    const float* w2_2 = (const float*)d_in[13];
    const float* b2_2 = (const float*)d_in[14];
    const float* w1_3 = (const float*)d_in[15];
    const float* b1_3 = (const float*)d_in[16];
    const float* w2_3 = (const float*)d_in[17];

    float *p_t, *p_a, *p_h0, *p_h1;
    cudaGetSymbolAddress((void**)&p_t,  g_t);
    cudaGetSymbolAddress((void**)&p_a,  g_a);
    cudaGetSymbolAddress((void**)&p_h0, g_h0);
    cudaGetSymbolAddress((void**)&p_h1, g_h1);

    dim3 cg(CHN, 6);
    const int EB = (CHN * HW + 255) / 256;

    pre0_kernel<<<(2 * HW + 255) / 256, 256>>>(x);
    conv_kernel<<<cg, 128>>>(p_t, 2,   w1_0, b1_0, nullptr, 0, 1, p_a);
    conv_kernel<<<cg, 128>>>(p_a, CHN, w2_0, b2_0, x,       5, 0, p_h0);

    pre_kernel<<<EB, 256>>>(p_h0, 0.7071067811865475f);
    conv_kernel<<<cg, 128>>>(p_t, CHN, w1_1, b1_1, nullptr, 0, 1, p_a);
    conv_kernel<<<cg, 128>>>(p_a, CHN, w2_1, b2_1, p_h0,    0, 0, p_h1);

    pre_kernel<<<EB, 256>>>(p_h1, 0.5773502691896258f);
    conv_kernel<<<cg, 128>>>(p_t, CHN, w1_2, b1_2, nullptr, 0, 1, p_a);
    conv_kernel<<<cg, 128>>>(p_a, CHN, w2_2, b2_2, p_h1,    0, 0, p_h0);

    pre_kernel<<<EB, 256>>>(p_h0, 0.5f);
    conv_kernel<<<cg, 128>>>(p_t, CHN, w1_3, b1_3, nullptr, 0, 1, p_a);
    conv_kernel<<<cg, 128>>>(p_a, CHN, w2_3, nullptr, p_h0, 0, 0, p_h1);

    scale_kernel<<<EB, 256>>>(p_h1);
    logj_kernel<<<1, TPB>>>();
    nonzero_kernel<<<1, 1024>>>(x);
    buildA_kernel<<<NA, TPB>>>(Fvv, Fhh);
    tridiag_kernel<<<GTRI, TPB>>>((float*)d_out);
}

// round 10
// speedup vs baseline: 1.6947x; 1.4444x over previous
#include <cuda_runtime.h>
#include <math.h>

#define HW    2304
#define MV    4608
#define CHN   64
#define NT2C  48
#define NOCC  1024
#define NA    1048
#define GTRI  148
#define TPB   256

__device__ float g_t [CHN*HW];
__device__ float g_a [CHN*HW];
__device__ float g_h0[CHN*HW];
__device__ float g_h1[CHN*HW];
__device__ float g_A[(size_t)NA*NA];
__device__ float g_u2[2][NA];
__device__ int   g_n[NOCC];
__device__ float g_logJ;
__device__ unsigned g_cnt = 0;
__device__ volatile unsigned g_gen;

__device__ __forceinline__ float gelu_f(float x) {
    float x3 = x * x * x;
    return 0.5f * x * (1.f + tanhf(0.7978845608028654f * (x + 0.044715f * x3)));
}

__device__ __forceinline__ float warp_sum(float v) {
    #pragma unroll
    for (int o = 16; o > 0; o >>= 1) v += __shfl_down_sync(0xffffffffu, v, o);
    return v;
}

__device__ __forceinline__ void gridbar() {
    __syncthreads();
    if (threadIdx.x == 0) {
        __threadfence();
        unsigned gen = g_gen;
        unsigned a = atomicAdd(&g_cnt, 1u);
        if (a == gridDim.x - 1) {
            g_cnt = 0;
            __threadfence();
            g_gen = gen + 1;
        } else {
            while (g_gen == gen) { }
        }
        __threadfence();
    }
    __syncthreads();
}

// ----------------------------- CNN ----------------------------------------
__global__ void pre0_kernel(const float* __restrict__ x) {
    int i = blockIdx.x * blockDim.x + threadIdx.x;
    if (i < 2 * HW) g_t[i] = x[i] * 0.7071067811865475f;
}

__global__ void pre_kernel(const float* __restrict__ h, float scale) {
    int i = blockIdx.x * blockDim.x + threadIdx.x;
    if (i < CHN * HW) g_t[i] = gelu_f(h[i] * scale);
}

__global__ void scale_kernel(const float* __restrict__ h) {
    int i = blockIdx.x * blockDim.x + threadIdx.x;
    if (i < CHN * HW) g_a[i] = h[i] * 0.4472135954999579f;
}

__global__ void conv_kernel(const float* __restrict__ xin, int IC,
                            const float* __restrict__ w,
                            const float* __restrict__ bias,
                            const float* __restrict__ res, int res_shift,
                            int do_gelu,
                            float* __restrict__ yout)
{
    __shared__ float sw[CHN * 9];
    int o = blockIdx.x;
    int t = threadIdx.x;
    for (int i = t; i < IC * 9; i += blockDim.x) sw[i] = w[o * IC * 9 + i];
    __syncthreads();

    int idx = blockIdx.y * 128 + t;
    int row = idx >> 4;
    int c0  = (idx & 15) * 3;
    int rm = (row == 0)  ? 47 : row - 1;
    int rp = (row == 47) ? 0  : row + 1;
    int cm = (c0 == 0)   ? 47 : c0 - 1;
    int c3 = (c0 == 45)  ? 0  : c0 + 3;

    float a0 = 0.f, a1 = 0.f, a2 = 0.f;
    int rows3[3] = { rm, row, rp };
    for (int ic = 0; ic < IC; ic++) {
        const float* xp = xin + ic * HW;
        const float* wp = sw + ic * 9;
        #pragma unroll
        for (int rr = 0; rr < 3; rr++) {
            const float* xr = xp + rows3[rr] * 48;
            float xa = xr[cm], xb = xr[c0], xc = xr[c0 + 1], xd = xr[c0 + 2], xe = xr[c3];
            float w0 = wp[rr * 3], w1 = wp[rr * 3 + 1], w2 = wp[rr * 3 + 2];
            a0 += w0 * xa + w1 * xb + w2 * xc;
            a1 += w0 * xb + w1 * xc + w2 * xd;
            a2 += w0 * xc + w1 * xd + w2 * xe;
        }
    }
    float bb = bias ? bias[o] : 0.f;
    a0 += bb; a1 += bb; a2 += bb;
    if (do_gelu) { a0 = gelu_f(a0); a1 = gelu_f(a1); a2 = gelu_f(a2); }
    int p = row * 48 + c0;
    if (res) {
        const float* rr_ = res + (o >> res_shift) * HW;
        a0 += rr_[p]; a1 += rr_[p + 1]; a2 += rr_[p + 2];
    }
    float* yp = yout + o * HW + p;
    yp[0] = a0; yp[1] = a1; yp[2] = a2;
}

__global__ void logj_kernel() {
    int t = threadIdx.x;
    float p = 0.f;
    for (int i = NT2C * HW + t; i < CHN * HW; i += TPB) p += g_a[i];
    p = warp_sum(p);
    __shared__ float sp[8];
    if ((t & 31) == 0) sp[t >> 5] = p;
    __syncthreads();
    if (t == 0) {
        float s = 0.f;
        for (int q = 0; q < 8; q++) s += sp[q];
        g_logJ = s;
    }
}

__global__ void nonzero_kernel(const float* __restrict__ x) {
    __shared__ int sc[1024];
    __shared__ int sbase;
    int t = threadIdx.x;
    if (t == 0) sbase = 0;
    __syncthreads();
    for (int c = 0; c < 5; c++) {
        int i = c * 1024 + t;
        int f = (i < MV && x[i] > 0.f) ? 1 : 0;
        sc[t] = f;
        __syncthreads();
        for (int off = 1; off < 1024; off <<= 1) {
            int v = (t >= off) ? sc[t - off] : 0;
            __syncthreads();
            sc[t] += v;
            __syncthreads();
        }
        if (f) {
            int pos = sbase + sc[t] - 1;
            if (pos < NOCC) g_n[pos] = i;
        }
        __syncthreads();
        if (t == 0) sbase += sc[1023];
        __syncthreads();
    }
}

__global__ void buildA_kernel(const float* __restrict__ Fvv,
                              const float* __restrict__ Fhh)
{
    int i = blockIdx.x;
    float* Ar = g_A + (size_t)i * NA;
    if (i < NOCC) {
        int ni = g_n[i];
        for (int j = threadIdx.x; j < NA; j += TPB) {
            float v;
            if (j < NOCC) {
                int nj = g_n[j];
                v = 0.5f * (Fvv[(size_t)ni * MV + nj] - Fvv[(size_t)nj * MV + ni]);
            } else {
                v = g_a[(j - NOCC) * MV + ni];
            }
            Ar[j] = v;
        }
    } else {
        int a = i - NOCC;
        for (int j = threadIdx.x; j < NA; j += TPB) {
            float v;
            if (j < NOCC) {
                int nj = g_n[j];
                v = -g_a[a * MV + nj];
            } else {
                int b = j - NOCC;
                v = 0.5f * (Fhh[a * 24 + b] - Fhh[b * 24 + a]);
            }
            Ar[j] = v;
        }
    }
}

// ---------------- persistent skew-Householder tridiagonalization -----------
// One grid barrier per step. Fused pass: each warp owns one trailing row,
// applies the rank-2 update for step k and accumulates the matvec for step
// k+1 in a single LDG.128/STG.128 sweep. v_{k+1} is rebuilt redundantly per
// CTA from the stale pivot row + rank-2 correction. u is double-buffered.
// All A/u traffic is __ldcg/__stcg (L2-only): row ownership rotates across
// CTAs and L1 is not coherent.
__global__ void __launch_bounds__(TPB, 1) tridiag_kernel(float* __restrict__ out)
{
    const int cta = blockIdx.x, t = threadIdx.x;
    const int w = t >> 5, lane = t & 31;
    __shared__ float sv[2][NA];     // v_k (parity k&1) and v_{k+1}
    __shared__ float su[NA];        // u_k
    __shared__ float sp[8];
    __shared__ float s_red;

    float sign_acc = 1.f;
    double logs = 0.0;

    // ---- pre-step: build v_0 from row 0 and compute u_0 = A v_0 (no update)
    {
        const float* row0 = g_A;
        float part = 0.f;
        for (int j = 1 + t; j < NA; j += TPB) {
            float xx = -__ldcg(row0 + j);
            sv[0][j] = xx;
            part += xx * xx;
        }
        if (t == 0) sv[0][0] = 0.f;
        part = warp_sum(part);
        if (lane == 0) sp[w] = part;
        __syncthreads();
        if (t == 0) { float a = 0.f; for (int q = 0; q < 8; q++) a += sp[q]; s_red = a; }
        __syncthreads();
        float norm2 = s_red;
        float x1 = sv[0][1];
        float s = (x1 >= 0.f) ? 1.f : -1.f;
        float normx = sqrtf(norm2);
        float vnsq = 2.f * norm2 + 2.f * s * normx * x1;
        bool ok = (vnsq > 0.f);
        float inv = ok ? rsqrtf(vnsq) : 0.f;
        if (ok) sign_acc = -sign_acc;
        sign_acc *= s;                         // k=0 even
        logs += log((double)normx);
        __syncthreads();
        if (t == 0) sv[0][1] = x1 + s * normx;
        for (int j = 1 + t; j < NA; j += TPB) sv[0][j] *= inv;
        __syncthreads();

        int j = 1 + cta * 8 + w;
        if (j < NA) {
            const float* rj = g_A + (size_t)j * NA;
            float acc = 0.f;
            for (int l = lane * 4; l < NA; l += 128) {
                float4 a4 = __ldcg((const float4*)(rj + l));
                acc += a4.x * sv[0][l] + a4.y * sv[0][l + 1]
                     + a4.z * sv[0][l + 2] + a4.w * sv[0][l + 3];
            }
            acc = warp_sum(acc);
            if (lane == 0) __stcg(&g_u2[0][j], acc);
        }
        gridbar();
    }

    // ---- main loop: iteration k applies update k and produces v_{k+1}, u_{k+1}
    for (int k = 0; k < NA - 3; k++) {
        const int base2 = k + 2;
        const int cur = k & 1, nxt = cur ^ 1;
        float* sv_c = sv[cur];
        float* sv_n = sv[nxt];
        const int c0 = (k + 1) & ~3;           // aligned start covering col k+1

        // -- load u_k into smem (whole buffer, float4); zero overhang [c0,k+1)
        for (int l = t * 4; l < NA; l += TPB * 4) {
            float4 u4 = __ldcg((const float4*)(&g_u2[cur][l]));
            *(float4*)(su + l) = u4;
        }
        if (t < 4) { int z = c0 + t; if (z < k + 1) su[z] = 0.f; }
        __syncthreads();

        // -- build v_{k+1} from stale row k+1 + rank-2 correction (redundant)
        const float vk1 = sv_c[k + 1];
        const float uk1 = su[k + 1];
        const float* rowp = g_A + (size_t)(k + 1) * NA;
        float part = 0.f;
        for (int l = base2 + t; l < NA; l += TPB) {
            float xx = -(__ldcg(rowp + l) + 2.f * (vk1 * su[l] - uk1 * sv_c[l]));
            sv_n[l] = xx;
            part += xx * xx;
        }
        if (t < 4) { int z = base2 - 4 + t; if (z >= 0) sv_n[z] = 0.f; }
        part = warp_sum(part);
        if (lane == 0) sp[w] = part;
        __syncthreads();
        if (t == 0) { float a = 0.f; for (int q = 0; q < 8; q++) a += sp[q]; s_red = a; }
        __syncthreads();
        float norm2 = s_red;
        float x1 = sv_n[base2];
        float s = (x1 >= 0.f) ? 1.f : -1.f;
        float normx = sqrtf(norm2);
        float vnsq = 2.f * norm2 + 2.f * s * normx * x1;
        bool ok = (vnsq > 0.f);
        float inv = ok ? rsqrtf(vnsq) : 0.f;
        if (ok) sign_acc = -sign_acc;
        if (((k + 1) & 1) == 0) {              // step k+1 even
            sign_acc *= s;
            logs += log((double)normx);
        }
        __syncthreads();                       // all read x1 before modify
        if (t == 0) sv_n[base2] = x1 + s * normx;
        for (int l = base2 + t; l < NA; l += TPB) sv_n[l] *= inv;
        __syncthreads();

        // -- fused pass: update row j (step k) + matvec with v_{k+1}
        int j = base2 + cta * 8 + w;
        if (j < NA) {
            float* rj = g_A + (size_t)j * NA;
            const float vj2 = 2.f * sv_c[j];
            const float uj2 = 2.f * su[j];
            float acc = 0.f;
            for (int l = c0 + lane * 4; l < NA; l += 128) {
                float4 a4 = __ldcg((const float4*)(rj + l));
                a4.x += vj2 * su[l]     - uj2 * sv_c[l];
                a4.y += vj2 * su[l + 1] - uj2 * sv_c[l + 1];
                a4.z += vj2 * su[l + 2] - uj2 * sv_c[l + 2];
                a4.w += vj2 * su[l + 3] - uj2 * sv_c[l + 3];
                __stcg((float4*)(rj + l), a4);
                acc += a4.x * sv_n[l]     + a4.y * sv_n[l + 1]
                     + a4.z * sv_n[l + 2] + a4.w * sv_n[l + 3];
            }
            acc = warp_sum(acc);
            if (lane == 0) __stcg(&g_u2[nxt][j], acc);
        }
        gridbar();
    }

    // ---- final step (k = NA-3): only element [NA-2, NA-1] matters
    if (cta == 0 && t == 0) {
        const int pl = (NA - 3) & 1;           // parity of last v/u
        float a_old = __ldcg(&g_A[(size_t)(NA - 2) * NA + (NA - 1)]);
        float v1 = sv[pl][NA - 2], v2 = sv[pl][NA - 1];
        float u1 = __ldcg(&g_u2[pl][NA - 2]);
        float u2 = __ldcg(&g_u2[pl][NA - 1]);
        float aL = a_old + 2.f * (v1 * u2 - u1 * v2);
        float sgn = sign_acc * ((aL >= 0.f) ? 1.f : -1.f);
        double tot = logs + log(fabs((double)aL)) + (double)g_logJ;
        out[0] = sgn;
        out[1] = (float)tot;
    }
}

extern "C" void kernel_launch(void* const* d_in, const int* in_sizes, int n_in,
                              void* d_out, int out_size) {
    const float* x   = (const float*)d_in[0];
    const float* Fvv = (const float*)d_in[1];
    const float* Fhh = (const float*)d_in[2];
    const float* w1_0 = (const float*)d_in[3];
    const float* b1_0 = (const float*)d_in[4];
    const float* w2_0 = (const float*)d_in[5];
    const float* b2_0 = (const float*)d_in[6];
    const float* w1_1 = (const float*)d_in[7];
    const float* b1_1 = (const float*)d_in[8];
    const float* w2_1 = (const float*)d_in[9];
    const float* b2_1 = (const float*)d_in[10];
    const float* w1_2 = (const float*)d_in[11];
    const float* b1_2 = (const float*)d_in[12];
    const float* w2_2 = (const float*)d_in[13];
    const float* b2_2 = (const float*)d_in[14];
    const float* w1_3 = (const float*)d_in[15];
    const float* b1_3 = (const float*)d_in[16];
    const float* w2_3 = (const float*)d_in[17];

    float *p_t, *p_a, *p_h0, *p_h1;
    cudaGetSymbolAddress((void**)&p_t,  g_t);
    cudaGetSymbolAddress((void**)&p_a,  g_a);
    cudaGetSymbolAddress((void**)&p_h0, g_h0);
    cudaGetSymbolAddress((void**)&p_h1, g_h1);

    dim3 cg(CHN, 6);
    const int EB = (CHN * HW + 255) / 256;

    pre0_kernel<<<(2 * HW + 255) / 256, 256>>>(x);
    conv_kernel<<<cg, 128>>>(p_t, 2,   w1_0, b1_0, nullptr, 0, 1, p_a);
    conv_kernel<<<cg, 128>>>(p_a, CHN, w2_0, b2_0, x,       5, 0, p_h0);

    pre_kernel<<<EB, 256>>>(p_h0, 0.7071067811865475f);
    conv_kernel<<<cg, 128>>>(p_t, CHN, w1_1, b1_1, nullptr, 0, 1, p_a);
    conv_kernel<<<cg, 128>>>(p_a, CHN, w2_1, b2_1, p_h0,    0, 0, p_h1);

    pre_kernel<<<EB, 256>>>(p_h1, 0.5773502691896258f);
    conv_kernel<<<cg, 128>>>(p_t, CHN, w1_2, b1_2, nullptr, 0, 1, p_a);
    conv_kernel<<<cg, 128>>>(p_a, CHN, w2_2, b2_2, p_h1,    0, 0, p_h0);

    pre_kernel<<<EB, 256>>>(p_h0, 0.5f);
    conv_kernel<<<cg, 128>>>(p_t, CHN, w1_3, b1_3, nullptr, 0, 1, p_a);
    conv_kernel<<<cg, 128>>>(p_a, CHN, w2_3, nullptr, p_h0, 0, 0, p_h1);

    scale_kernel<<<EB, 256>>>(p_h1);
    logj_kernel<<<1, TPB>>>();
    nonzero_kernel<<<1, 1024>>>(x);
    buildA_kernel<<<NA, TPB>>>(Fvv, Fhh);
    tridiag_kernel<<<GTRI, TPB>>>((float*)d_out);
}